// round 17
// baseline (speedup 1.0000x reference)
#include <cuda_runtime.h>

#define N_ 8
#define C_ 64
#define L_ 512
#define D_ 64
#define TI 16    // rows of i per band block
#define KP 68    // ks smem pitch: multiple of 4 (16B align), conflict-free
#define XP 79    // xb smem pitch: odd -> conflict-free

// dynamic smem layout (floats):
//   ks   [TI+63][KP]   : 0                  .. 5372
//   xb   [C_][XP]      : 5372               .. 10428
//   qa   [TI][64]      : 10428              .. 11452   (16B aligned: 10428%4==0)
//   wa_s [64]          : 11452              .. 11516
//   red_s[TI][2]       : 11516              .. 11548
//   v_s  [C_][TI+1]    : 11548              .. 12636
#define OFF_XB   5372
#define OFF_QA   10428
#define OFF_WA   11452
#define OFF_RED  11516
#define OFF_VS   11548
#define SMEM_FLOATS 12636
#define SMEM_BYTES  (SMEM_FLOATS * 4)

// scratch (static device globals — no allocation); 16B-aligned for float4 access
__device__ __align__(16) float g_qb[N_ * L_ * D_];  // q + bh
__device__ __align__(16) float g_kk[N_ * L_ * D_];  // k

// quad barrier: 2 row-pairs (128 threads) share one of the ids 1..8
#define QUAD_BAR(id) asm volatile("bar.sync %0, 128;" :: "r"(id) : "memory")

__device__ __forceinline__ float tanh_hw(float z) {
    float y; asm("tanh.approx.f32 %0, %1;" : "=f"(y) : "f"(z)); return y;
}
__device__ __forceinline__ float ex2_m(float z) {
    float y; asm("ex2.approx.f32 %0, %1;" : "=f"(y) : "f"(z)); return y;
}
__device__ __forceinline__ float rcp_m(float d) {
    float y; asm("rcp.approx.f32 %0, %1;" : "=f"(y) : "f"(d)); return y;
}

// ---------------------------------------------------------------------------
// Kernel 1: q = xt@Wt + bh, k = xt@Wx  (identical to R16 — proven)
// ---------------------------------------------------------------------------
__global__ void __launch_bounds__(512)
proj_kernel(const float* __restrict__ x,
            const float* __restrict__ Wx,
            const float* __restrict__ Wt,
            const float* __restrict__ bh) {
    asm volatile("griddepcontrol.launch_dependents;");
    __shared__ __align__(16) float wt[C_ * D_];
    __shared__ __align__(16) float wx[C_ * D_];
    __shared__ __align__(16) float xs[C_][36];
    int n  = blockIdx.x;
    int l0 = blockIdx.y << 5;
    int t  = threadIdx.x;

    ((float4*)wt)[t]       = ((const float4*)Wt)[t];
    ((float4*)wt)[t + 512] = ((const float4*)Wt)[t + 512];
    ((float4*)wx)[t]       = ((const float4*)Wx)[t];
    ((float4*)wx)[t + 512] = ((const float4*)Wx)[t + 512];
    {
        int c = t >> 3, l4 = (t & 7) << 2;
        *(float4*)&xs[c][l4] = *(const float4*)(x + (n * C_ + c) * L_ + l0 + l4);
    }
    __syncthreads();

    int dg = t >> 5, ll = t & 31;
    int d0 = dg << 2;
    float q0 = 0, q1 = 0, q2 = 0, q3 = 0, k0 = 0, k1 = 0, k2 = 0, k3 = 0;
#pragma unroll 8
    for (int c = 0; c < C_; c++) {
        float  xv  = xs[c][ll];
        float4 wt4 = *(const float4*)(wt + c * D_ + d0);
        float4 wx4 = *(const float4*)(wx + c * D_ + d0);
        q0 = fmaf(xv, wt4.x, q0); q1 = fmaf(xv, wt4.y, q1);
        q2 = fmaf(xv, wt4.z, q2); q3 = fmaf(xv, wt4.w, q3);
        k0 = fmaf(xv, wx4.x, k0); k1 = fmaf(xv, wx4.y, k1);
        k2 = fmaf(xv, wx4.z, k2); k3 = fmaf(xv, wx4.w, k3);
    }
    float4 b4 = *(const float4*)(bh + d0);
    int gi = (n * L_ + l0 + ll) * D_ + d0;
    float4 qo = { q0 + b4.x, q1 + b4.y, q2 + b4.z, q3 + b4.w };
    float4 ko = { k0, k1, k2, k3 };
    *(float4*)(g_qb + gi) = qo;
    *(float4*)(g_kk + gi) = ko;
}

// ---------------------------------------------------------------------------
// Kernel 2: banded scores + softmax + a + v. TI=16 rows, 2 warps per row.
// grid (N_, L_/TI) = 256 blocks, 1024 threads, 2 blocks/SM (dynamic smem 50.5KB).
// PDL overlap window now covers: xb staging + wa + a-output ZERO-FILL.
// Post-softmax writes only the band float4s. v_s is separate (no alias barrier).
// ---------------------------------------------------------------------------
__global__ void __launch_bounds__(1024, 2)
band_kernel(const float* __restrict__ x,
            const float* __restrict__ Wa,
            float* __restrict__ out) {
    extern __shared__ __align__(16) float sm[];
    float (*ks)[KP]     = (float (*)[KP])sm;
    float (*xb)[XP]     = (float (*)[XP])(sm + OFF_XB);
    float (*qa)[64]     = (float (*)[64])(sm + OFF_QA);
    float*  wa_s        = sm + OFF_WA;
    float (*red_s)[2]   = (float (*)[2])(sm + OFF_RED);
    float (*v_s)[TI+1]  = (float (*)[TI+1])(sm + OFF_VS);

    int n     = blockIdx.x;
    int i0    = blockIdx.y * TI;
    int t     = threadIdx.x;
    int jbase = i0 - 32;
    float* ablk = out + (size_t)N_ * C_ * L_ + (size_t)(n * L_ + i0) * L_;

    // ===== PDL overlap phase (independent of proj output) =====
    {   // x band staging
        int c = t >> 4, cb = t & 15;
        const float* xrow = x + (n * C_ + c) * L_;
#pragma unroll
        for (int k = 0; k < 5; k++) {
            int col = cb + (k << 4);
            if (col < XP) {
                int gj = jbase + col;
                xb[c][col] = ((unsigned)gj < (unsigned)L_) ? xrow[gj] : 0.f;
            }
        }
    }
    if (t < D_) wa_s[t] = Wa[t];
    // a-output zero-fill outside each row's band float4 range
    for (int idx = t; idx < TI * 128; idx += 1024) {
        int row = idx >> 7, q = idx & 127;
        int i   = i0 + row;
        int lo  = (i > 32 ? i - 32 : 0) >> 2;
        int hi  = (i + 31 < 511 ? i + 31 : 511) >> 2;
        if (q < lo || q > hi) {
            float4 z = { 0.f, 0.f, 0.f, 0.f };
            *(float4*)(ablk + (size_t)row * L_ + (q << 2)) = z;
        }
    }

    // ===== wait for proj's g_kk / g_qb =====
    asm volatile("griddepcontrol.wait;");

    for (int i4 = t; i4 < (TI + 63) * 16; i4 += 1024) {  // k band, float4
        int jj = i4 >> 4, d4 = (i4 & 15) << 2;
        int gj = jbase + jj;
        float4 v = { 0.f, 0.f, 0.f, 0.f };
        if ((unsigned)gj < (unsigned)L_)
            v = *(const float4*)(g_kk + ((n * L_ + gj) << 6) + d4);
        *(float4*)&ks[jj][d4] = v;
    }
    if (t < 256) ((float4*)qa)[t] = ((const float4*)(g_qb + (n * L_ + i0) * D_))[t];
    __syncthreads();

    int w = t >> 5, ln = t & 31;
    int w_row = w >> 1, h = w & 1;        // 2 warps per i-row
    int bar_id = 1 + (w_row >> 1);        // 2 row-pairs share a named barrier
    int i   = i0 + w_row;
    int jl  = h * 32 + ln;                // band offset 0..63
    int col = w_row + jl;                 // tile column 0..78
    int gj  = jbase + col;
    bool valid = (unsigned)gj < (unsigned)L_;

    // --- score: acc = sum_d wa_d * tanh(q_d + k_d); 4-way split accumulator ---
    const float* ksr = &ks[col][0];
    const float* qar = &qa[w_row][0];
    float a0 = 0.f, a1 = 0.f, a2 = 0.f, a3 = 0.f;
#pragma unroll
    for (int d4 = 0; d4 < D_; d4 += 4) {
        float4 kv = *(const float4*)(ksr + d4);
        float4 qv = *(const float4*)(qar + d4);
        float4 wv = *(const float4*)(wa_s + d4);
        a0 = fmaf(wv.x, tanh_hw(qv.x + kv.x), a0);
        a1 = fmaf(wv.y, tanh_hw(qv.y + kv.y), a1);
        a2 = fmaf(wv.z, tanh_hw(qv.z + kv.z), a2);
        a3 = fmaf(wv.w, tanh_hw(qv.w + kv.w), a3);
    }
    float acc = (a0 + a1) + (a2 + a3);

    // --- band softmax; no max subtraction (|acc| <= sum|wa|, no overflow) ---
    float e = valid ? ex2_m(acc * 1.442695040888963f) : 0.f;
    float s = e;
#pragma unroll
    for (int o = 16; o > 0; o >>= 1) s += __shfl_xor_sync(0xffffffffu, s, o);
    if (ln == 0) red_s[w_row][h] = s;
    QUAD_BAR(bar_id);
    float S = red_s[w_row][0] + red_s[w_row][1];
    float a = e * rcp_m(S + 1e-6f);
    qa[w_row][jl] = a;                    // q row dead: reuse as a row
    QUAD_BAR(bar_id);

    // --- band-only a write: float4 range [lo, hi], 17 lanes of the h=0 warp ---
    {
        int lo = (i > 32 ? i - 32 : 0) >> 2;
        int hi = (i + 31 < 511 ? i + 31 : 511) >> 2;
        int ecnt = hi - lo + 1;           // <= 17
        int e_id = jl;                    // 0..63 across the row's 2 warps
        if (e_id < ecnt) {
            int q   = lo + e_id;
            int idx = q << 2;
            int j0  = idx - i + 32;
            float4 vv;
            vv.x = ((unsigned)(j0)     < 64u) ? qa[w_row][j0]     : 0.f;
            vv.y = ((unsigned)(j0 + 1) < 64u) ? qa[w_row][j0 + 1] : 0.f;
            vv.z = ((unsigned)(j0 + 2) < 64u) ? qa[w_row][j0 + 2] : 0.f;
            vv.w = ((unsigned)(j0 + 3) < 64u) ? qa[w_row][j0 + 3] : 0.f;
            *(float4*)(ablk + (size_t)w_row * L_ + idx) = vv;
        }
    }

    // --- v[n, c, i]: lane handles c = jl (no block barrier needed: v_s separate) ---
    int c = jl;
    float vacc = 0.f;
#pragma unroll
    for (int j4 = 0; j4 < 64; j4 += 4) {
        float4 av = *(const float4*)(qar + j4);
        vacc = fmaf(av.x, xb[c][w_row + j4],     vacc);
        vacc = fmaf(av.y, xb[c][w_row + j4 + 1], vacc);
        vacc = fmaf(av.z, xb[c][w_row + j4 + 2], vacc);
        vacc = fmaf(av.w, xb[c][w_row + j4 + 3], vacc);
    }
    v_s[c][w_row] = vacc;
    __syncthreads();   // all rows' v_s ready

    // --- coalesced v store via transpose staging ---
    int c2 = t >> 4, il = t & 15;
    out[(n * C_ + c2) * L_ + i0 + il] = v_s[c2][il];
}

// ---------------------------------------------------------------------------
extern "C" void kernel_launch(void* const* d_in, const int* in_sizes, int n_in,
                              void* d_out, int out_size) {
    const float* x  = (const float*)d_in[0];
    const float* Wx = (const float*)d_in[1];
    const float* Wt = (const float*)d_in[2];
    const float* bh = (const float*)d_in[3];
    const float* Wa = (const float*)d_in[4];
    // d_in[5] = ba: cancels in softmax normalization, unused.
    float* out = (float*)d_out;

    // opt-in dynamic smem > 48KB (idempotent; not a stream op)
    cudaFuncSetAttribute(band_kernel,
                         cudaFuncAttributeMaxDynamicSharedMemorySize, SMEM_BYTES);

    proj_kernel<<<dim3(N_, 16), 512>>>(x, Wx, Wt, bh);

    cudaLaunchConfig_t cfg = {};
    cfg.gridDim  = dim3(N_, L_ / TI);
    cfg.blockDim = dim3(1024);
    cfg.dynamicSmemBytes = SMEM_BYTES;
    cfg.stream = 0;
    cudaLaunchAttribute attrs[1];
    attrs[0].id = cudaLaunchAttributeProgrammaticStreamSerialization;
    attrs[0].val.programmaticStreamSerializationAllowed = 1;
    cfg.attrs = attrs;
    cfg.numAttrs = 1;
    cudaLaunchKernelEx(&cfg, band_kernel, x, Wa, out);
}